// round 2
// baseline (speedup 1.0000x reference)
#include <cuda_runtime.h>
#include <cuda_bf16.h>
#include <math.h>

// NNUE HalfKA inference:
//   stm_ft[b]  = sum_i (W_ft[stm_feat[b,i]]  + W_fft[stm_feat[b,i]  % 768]) * v[b,i]  + b_ft + b_fft
//   nstm_ft[b] = sum_i (W_ft[nstm_feat[b,i]] + W_fft[nstm_feat[b,i] % 768]) * v[b,i]  + b_ft + b_fft
//   out[b] = sigmoid( clip01(stm_ft) . W_out[0:1024] + clip01(nstm_ft) . W_out[1024:2048] + b_out )
//
// Shapes: B=8192, FPP=32, FT_OUT=1024, N_FEAT=49152, N_VFEAT=768.

#define FT_OUT  1024
#define FPP     32
#define NVFEAT  768
#define NTHREADS 256   // 256 threads * float4 = 1024 = one full row

__global__ __launch_bounds__(NTHREADS)
void nnue_halfka_kernel(
    const float* __restrict__ values,     // [NNZ]
    const int*   __restrict__ stm_feat,   // [NNZ]
    const int*   __restrict__ nstm_feat,  // [NNZ]
    const float* __restrict__ W_ft,       // [N_FEAT, 1024]
    const float* __restrict__ b_ft,       // [1024]
    const float* __restrict__ W_fft,      // [N_VFEAT, 1024]
    const float* __restrict__ b_fft,      // [1024]
    const float* __restrict__ W_out,      // [2048, 1]
    const float* __restrict__ b_out,      // [1]
    float*       __restrict__ out)        // [B]
{
    __shared__ int   s_feat[2 * FPP];
    __shared__ float s_val[FPP];
    __shared__ float s_red[NTHREADS / 32];

    const int b   = blockIdx.x;
    const int tid = threadIdx.x;

    if (tid < FPP) {
        s_feat[tid]       = stm_feat[b * FPP + tid];
        s_feat[FPP + tid] = nstm_feat[b * FPP + tid];
        s_val[tid]        = values[b * FPP + tid];
    }
    __syncthreads();

    // Each thread owns 4 consecutive output dims: [4*tid, 4*tid+4)
    const int d = tid * 4;

    float4 bias;
    {
        float4 bf  = *(const float4*)(b_ft + d);
        float4 bff = *(const float4*)(b_fft + d);
        bias = make_float4(bf.x + bff.x, bf.y + bff.y, bf.z + bff.z, bf.w + bff.w);
    }

    float4 acc_s = bias;
    float4 acc_n = bias;

    // ---- STM side ----
    #pragma unroll 4
    for (int i = 0; i < FPP; i++) {
        const int   f = s_feat[i];
        const float v = s_val[i];
        const int  fv = f % NVFEAT;
        float4 w  = __ldg((const float4*)(W_ft  + (size_t)f  * FT_OUT) + tid);
        float4 w2 = __ldg((const float4*)(W_fft + (size_t)fv * FT_OUT) + tid);
        acc_s.x = fmaf(w.x + w2.x, v, acc_s.x);
        acc_s.y = fmaf(w.y + w2.y, v, acc_s.y);
        acc_s.z = fmaf(w.z + w2.z, v, acc_s.z);
        acc_s.w = fmaf(w.w + w2.w, v, acc_s.w);
    }

    // ---- NSTM side ----
    #pragma unroll 4
    for (int i = 0; i < FPP; i++) {
        const int   f = s_feat[FPP + i];
        const float v = s_val[i];
        const int  fv = f % NVFEAT;
        float4 w  = __ldg((const float4*)(W_ft  + (size_t)f  * FT_OUT) + tid);
        float4 w2 = __ldg((const float4*)(W_fft + (size_t)fv * FT_OUT) + tid);
        acc_n.x = fmaf(w.x + w2.x, v, acc_n.x);
        acc_n.y = fmaf(w.y + w2.y, v, acc_n.y);
        acc_n.z = fmaf(w.z + w2.z, v, acc_n.z);
        acc_n.w = fmaf(w.w + w2.w, v, acc_n.w);
    }

    // clip to [0,1]
    acc_s.x = fminf(fmaxf(acc_s.x, 0.f), 1.f);
    acc_s.y = fminf(fmaxf(acc_s.y, 0.f), 1.f);
    acc_s.z = fminf(fmaxf(acc_s.z, 0.f), 1.f);
    acc_s.w = fminf(fmaxf(acc_s.w, 0.f), 1.f);
    acc_n.x = fminf(fmaxf(acc_n.x, 0.f), 1.f);
    acc_n.y = fminf(fmaxf(acc_n.y, 0.f), 1.f);
    acc_n.z = fminf(fmaxf(acc_n.z, 0.f), 1.f);
    acc_n.w = fminf(fmaxf(acc_n.w, 0.f), 1.f);

    // output layer partial dot
    float4 wo_s = *(const float4*)(W_out + d);
    float4 wo_n = *(const float4*)(W_out + FT_OUT + d);
    float p = acc_s.x * wo_s.x + acc_s.y * wo_s.y + acc_s.z * wo_s.z + acc_s.w * wo_s.w
            + acc_n.x * wo_n.x + acc_n.y * wo_n.y + acc_n.z * wo_n.z + acc_n.w * wo_n.w;

    // warp reduce
    #pragma unroll
    for (int off = 16; off > 0; off >>= 1)
        p += __shfl_down_sync(0xffffffffu, p, off);
    if ((tid & 31) == 0) s_red[tid >> 5] = p;
    __syncthreads();

    if (tid < (NTHREADS / 32)) {
        float q = s_red[tid];
        #pragma unroll
        for (int off = (NTHREADS / 64); off > 0; off >>= 1)
            q += __shfl_down_sync(0xffu, q, off);
        if (tid == 0) {
            float x = q + b_out[0];
            out[b] = 1.0f / (1.0f + expf(-x));
        }
    }
}

extern "C" void kernel_launch(void* const* d_in, const int* in_sizes, int n_in,
                              void* d_out, int out_size) {
    // metadata order:
    // 0 values, 1 stm_feat, 2 nstm_feat, 3 batch_idx, 4 W_ft, 5 b_ft,
    // 6 W_fft, 7 b_fft, 8 W_out, 9 b_out, 10 size
    const float* values    = (const float*)d_in[0];
    const int*   stm_feat  = (const int*)d_in[1];
    const int*   nstm_feat = (const int*)d_in[2];
    const float* W_ft      = (const float*)d_in[4];
    const float* b_ft      = (const float*)d_in[5];
    const float* W_fft     = (const float*)d_in[6];
    const float* b_fft     = (const float*)d_in[7];
    const float* W_out     = (const float*)d_in[8];
    const float* b_out     = (const float*)d_in[9];
    float* out = (float*)d_out;

    const int B = out_size;  // 8192

    nnue_halfka_kernel<<<B, NTHREADS>>>(values, stm_feat, nstm_feat,
                                        W_ft, b_ft, W_fft, b_fft,
                                        W_out, b_out, out);
}

// round 5
// speedup vs baseline: 1.7511x; 1.7511x over previous
#include <cuda_runtime.h>
#include <cuda_bf16.h>
#include <math.h>

// NNUE HalfKA inference, two-phase:
//  Phase 1: g_comb[f] = bf16(W_ft[f] + W_fft[f % 768])   (96 MB, fits 126 MB L2)
//  Phase 2: per batch element, gather 2x32 bf16 rows from g_comb (mostly L2 hits),
//           add fp32 biases, clip, output dot, sigmoid.
//
// Shapes: B=8192, FPP=32, FT_OUT=1024, N_FEAT=49152, N_VFEAT=768.

#define FT_OUT   1024
#define FPP      32
#define NVFEAT   768
#define NFEAT    49152
#define NTHREADS 256   // 256 threads * 4 dims = 1024 = one full row

// 96 MB combined bf16 table (static device scratch — no runtime allocation)
__device__ __nv_bfloat16 g_comb[(size_t)NFEAT * FT_OUT];

// ---------------- Phase 1: build combined bf16 table ----------------
__global__ __launch_bounds__(NTHREADS)
void build_comb_kernel(const float* __restrict__ W_ft,
                       const float* __restrict__ W_fft)
{
    const int f = blockIdx.x;            // 0..NFEAT-1
    const int c = threadIdx.x * 4;       // 0..1020
    const size_t base = (size_t)f * FT_OUT + c;
    const float4 a = *(const float4*)(W_ft + base);
    const float4 v = __ldg((const float4*)(W_fft + (size_t)(f % NVFEAT) * FT_OUT + c));

    __nv_bfloat162 lo = __floats2bfloat162_rn(a.x + v.x, a.y + v.y);
    __nv_bfloat162 hi = __floats2bfloat162_rn(a.z + v.z, a.w + v.w);
    uint2 pack;
    pack.x = *(unsigned int*)&lo;
    pack.y = *(unsigned int*)&hi;
    *(uint2*)(g_comb + base) = pack;
}

// ---------------- Phase 2: gather + epilogue ----------------
__global__ __launch_bounds__(NTHREADS)
void nnue_gather_kernel(
    const float* __restrict__ values,     // [NNZ]
    const int*   __restrict__ stm_feat,   // [NNZ]
    const int*   __restrict__ nstm_feat,  // [NNZ]
    const float* __restrict__ b_ft,       // [1024]
    const float* __restrict__ b_fft,      // [1024]
    const float* __restrict__ W_out,      // [2048]
    const float* __restrict__ b_out,      // [1]
    float*       __restrict__ out)        // [B]
{
    __shared__ int   s_feat[2 * FPP];
    __shared__ float s_val[FPP];
    __shared__ float s_red[NTHREADS / 32];

    const int b   = blockIdx.x;
    const int tid = threadIdx.x;

    if (tid < FPP) {
        s_feat[tid]       = stm_feat[b * FPP + tid];
        s_feat[FPP + tid] = nstm_feat[b * FPP + tid];
        s_val[tid]        = values[b * FPP + tid];
    }
    __syncthreads();

    // Each thread owns 4 consecutive output dims: [4*tid, 4*tid+4)
    const int d = tid * 4;

    float4 bias;
    {
        float4 bf  = *(const float4*)(b_ft + d);
        float4 bff = *(const float4*)(b_fft + d);
        bias = make_float4(bf.x + bff.x, bf.y + bff.y, bf.z + bff.z, bf.w + bff.w);
    }

    float4 acc_s = bias;
    float4 acc_n = bias;

    const __nv_bfloat16* __restrict__ comb = g_comb;

    // Interleave both sides: 2 independent 8B loads per iter, unroll 4 -> 8 in flight
    #pragma unroll 4
    for (int i = 0; i < FPP; i++) {
        const float v  = s_val[i];
        const int   fs = s_feat[i];
        const int   fn = s_feat[FPP + i];

        uint2 ps = *(const uint2*)(comb + (size_t)fs * FT_OUT + d);
        uint2 pn = *(const uint2*)(comb + (size_t)fn * FT_OUT + d);

        float2 s01 = __bfloat1622float2(*(__nv_bfloat162*)&ps.x);
        float2 s23 = __bfloat1622float2(*(__nv_bfloat162*)&ps.y);
        float2 n01 = __bfloat1622float2(*(__nv_bfloat162*)&pn.x);
        float2 n23 = __bfloat1622float2(*(__nv_bfloat162*)&pn.y);

        acc_s.x = fmaf(s01.x, v, acc_s.x);
        acc_s.y = fmaf(s01.y, v, acc_s.y);
        acc_s.z = fmaf(s23.x, v, acc_s.z);
        acc_s.w = fmaf(s23.y, v, acc_s.w);
        acc_n.x = fmaf(n01.x, v, acc_n.x);
        acc_n.y = fmaf(n01.y, v, acc_n.y);
        acc_n.z = fmaf(n23.x, v, acc_n.z);
        acc_n.w = fmaf(n23.y, v, acc_n.w);
    }

    // clip to [0,1]
    acc_s.x = fminf(fmaxf(acc_s.x, 0.f), 1.f);
    acc_s.y = fminf(fmaxf(acc_s.y, 0.f), 1.f);
    acc_s.z = fminf(fmaxf(acc_s.z, 0.f), 1.f);
    acc_s.w = fminf(fmaxf(acc_s.w, 0.f), 1.f);
    acc_n.x = fminf(fmaxf(acc_n.x, 0.f), 1.f);
    acc_n.y = fminf(fmaxf(acc_n.y, 0.f), 1.f);
    acc_n.z = fminf(fmaxf(acc_n.z, 0.f), 1.f);
    acc_n.w = fminf(fmaxf(acc_n.w, 0.f), 1.f);

    // output layer partial dot
    float4 wo_s = *(const float4*)(W_out + d);
    float4 wo_n = *(const float4*)(W_out + FT_OUT + d);
    float p = acc_s.x * wo_s.x + acc_s.y * wo_s.y + acc_s.z * wo_s.z + acc_s.w * wo_s.w
            + acc_n.x * wo_n.x + acc_n.y * wo_n.y + acc_n.z * wo_n.z + acc_n.w * wo_n.w;

    // warp reduce
    #pragma unroll
    for (int off = 16; off > 0; off >>= 1)
        p += __shfl_down_sync(0xffffffffu, p, off);
    if ((tid & 31) == 0) s_red[tid >> 5] = p;
    __syncthreads();

    if (tid < (NTHREADS / 32)) {
        float q = s_red[tid];
        #pragma unroll
        for (int off = (NTHREADS / 64); off > 0; off >>= 1)
            q += __shfl_down_sync(0xffu, q, off);
        if (tid == 0) {
            float x = q + b_out[0];
            out[b] = 1.0f / (1.0f + expf(-x));
        }
    }
}

extern "C" void kernel_launch(void* const* d_in, const int* in_sizes, int n_in,
                              void* d_out, int out_size) {
    // metadata order:
    // 0 values, 1 stm_feat, 2 nstm_feat, 3 batch_idx, 4 W_ft, 5 b_ft,
    // 6 W_fft, 7 b_fft, 8 W_out, 9 b_out, 10 size
    const float* values    = (const float*)d_in[0];
    const int*   stm_feat  = (const int*)d_in[1];
    const int*   nstm_feat = (const int*)d_in[2];
    const float* W_ft      = (const float*)d_in[4];
    const float* b_ft      = (const float*)d_in[5];
    const float* W_fft     = (const float*)d_in[6];
    const float* b_fft     = (const float*)d_in[7];
    const float* W_out     = (const float*)d_in[8];
    const float* b_out     = (const float*)d_in[9];
    float* out = (float*)d_out;

    const int B = out_size;  // 8192

    build_comb_kernel<<<NFEAT, NTHREADS>>>(W_ft, W_fft);
    nnue_gather_kernel<<<B, NTHREADS>>>(values, stm_feat, nstm_feat,
                                        b_ft, b_fft, W_out, b_out, out);
}

// round 6
// speedup vs baseline: 1.8962x; 1.0828x over previous
#include <cuda_runtime.h>
#include <cuda_bf16.h>
#include <math.h>

// NNUE HalfKA inference, two-phase:
//  Phase 1: g_comb[f] = bf16(W_ft[f] + W_fft[f % 768])   (96 MB, mostly L2-resident)
//  Phase 2: per batch element, gather 2x32 bf16 rows from g_comb,
//           fp32 (packed f32x2) accumulate, add biases, clip, output dot, sigmoid.
//
// Shapes: B=8192, FPP=32, FT_OUT=1024, N_FEAT=49152, N_VFEAT=768.

#define FT_OUT   1024
#define FPP      32
#define NVFEAT   768
#define NFEAT    49152
#define BLD_THREADS 256
#define GTH_THREADS 128   // 128 threads * 8 dims (16 B bf16) = one 2048 B row

// 96 MB combined bf16 table (static device scratch — no runtime allocation)
__device__ __nv_bfloat16 g_comb[(size_t)NFEAT * FT_OUT];

// ---- packed f32x2 helpers (sm_103a FFMA2 path; ptxas won't emit from C++) ----
__device__ __forceinline__ unsigned long long pack_f2(float a, float b) {
    unsigned long long r;
    asm("mov.b64 %0, {%1, %2};" : "=l"(r) : "f"(a), "f"(b));
    return r;
}
__device__ __forceinline__ void unpack_f2(unsigned long long r, float& a, float& b) {
    asm("mov.b64 {%0, %1}, %2;" : "=f"(a), "=f"(b) : "l"(r));
}
__device__ __forceinline__ unsigned long long fma_f2(unsigned long long a,
                                                     unsigned long long b,
                                                     unsigned long long c) {
    unsigned long long d;
    asm("fma.rn.f32x2 %0, %1, %2, %3;" : "=l"(d) : "l"(a), "l"(b), "l"(c));
    return d;
}
// bf16x2 (one u32) -> packed f32x2 (lo = bits<<16, hi = bits&0xffff0000)
__device__ __forceinline__ unsigned long long bf2_to_f2(unsigned int p) {
    unsigned long long r;
    asm("{\n\t"
        ".reg .b32 lo, hi;\n\t"
        "shl.b32 lo, %1, 16;\n\t"
        "and.b32 hi, %1, 0xffff0000;\n\t"
        "mov.b64 %0, {lo, hi};\n\t"
        "}" : "=l"(r) : "r"(p));
    return r;
}

// ---------------- Phase 1: build combined bf16 table ----------------
__global__ __launch_bounds__(BLD_THREADS)
void build_comb_kernel(const float* __restrict__ W_ft,
                       const float* __restrict__ W_fft)
{
    const int f = blockIdx.x;            // 0..NFEAT-1
    const int c = threadIdx.x * 4;       // 0..1020
    const size_t base = (size_t)f * FT_OUT + c;
    // W_ft is streamed exactly once: evict-first so it doesn't thrash the
    // freshly written comb table out of L2.
    const float4 a = __ldcs((const float4*)(W_ft + base));
    const float4 v = __ldg((const float4*)(W_fft + (size_t)(f % NVFEAT) * FT_OUT + c));

    __nv_bfloat162 lo = __floats2bfloat162_rn(a.x + v.x, a.y + v.y);
    __nv_bfloat162 hi = __floats2bfloat162_rn(a.z + v.z, a.w + v.w);
    uint2 pack;
    pack.x = *(unsigned int*)&lo;
    pack.y = *(unsigned int*)&hi;
    *(uint2*)(g_comb + base) = pack;
}

// ---------------- Phase 2: gather + epilogue ----------------
__global__ __launch_bounds__(GTH_THREADS)
void nnue_gather_kernel(
    const float* __restrict__ values,     // [NNZ]
    const int*   __restrict__ stm_feat,   // [NNZ]
    const int*   __restrict__ nstm_feat,  // [NNZ]
    const float* __restrict__ b_ft,       // [1024]
    const float* __restrict__ b_fft,      // [1024]
    const float* __restrict__ W_out,      // [2048]
    const float* __restrict__ b_out,      // [1]
    float*       __restrict__ out)        // [B]
{
    __shared__ int   s_off[2 * FPP];      // byte offsets into g_comb
    __shared__ float s_val[FPP];
    __shared__ float s_red[GTH_THREADS / 32];

    const int b   = blockIdx.x;
    const int tid = threadIdx.x;

    if (tid < FPP) {
        s_off[tid]       = stm_feat[b * FPP + tid] << 11;   // *2048 B/row
        s_off[FPP + tid] = nstm_feat[b * FPP + tid] << 11;
        s_val[tid]       = values[b * FPP + tid];
    }
    __syncthreads();

    // Each thread owns 8 consecutive dims: [8*tid, 8*tid+8), i.e. 16 bytes bf16
    const int d = tid * 8;
    const char* base = (const char*)g_comb + tid * 16;

    // biases -> packed f32x2 accumulators
    unsigned long long acc_s[4], acc_n[4];
    {
        float4 bf0  = *(const float4*)(b_ft  + d);
        float4 bf1  = *(const float4*)(b_ft  + d + 4);
        float4 bb0  = *(const float4*)(b_fft + d);
        float4 bb1  = *(const float4*)(b_fft + d + 4);
        acc_s[0] = pack_f2(bf0.x + bb0.x, bf0.y + bb0.y);
        acc_s[1] = pack_f2(bf0.z + bb0.z, bf0.w + bb0.w);
        acc_s[2] = pack_f2(bf1.x + bb1.x, bf1.y + bb1.y);
        acc_s[3] = pack_f2(bf1.z + bb1.z, bf1.w + bb1.w);
        acc_n[0] = acc_s[0]; acc_n[1] = acc_s[1];
        acc_n[2] = acc_s[2]; acc_n[3] = acc_s[3];
    }

    #pragma unroll 4
    for (int i = 0; i < FPP; i++) {
        const float v = s_val[i];
        const unsigned long long vv = pack_f2(v, v);
        const int os = s_off[i];
        const int on = s_off[FPP + i];

        uint4 ps = *(const uint4*)(base + os);   // 8 bf16 stm weights
        uint4 pn = *(const uint4*)(base + on);   // 8 bf16 nstm weights

        acc_s[0] = fma_f2(bf2_to_f2(ps.x), vv, acc_s[0]);
        acc_s[1] = fma_f2(bf2_to_f2(ps.y), vv, acc_s[1]);
        acc_s[2] = fma_f2(bf2_to_f2(ps.z), vv, acc_s[2]);
        acc_s[3] = fma_f2(bf2_to_f2(ps.w), vv, acc_s[3]);
        acc_n[0] = fma_f2(bf2_to_f2(pn.x), vv, acc_n[0]);
        acc_n[1] = fma_f2(bf2_to_f2(pn.y), vv, acc_n[1]);
        acc_n[2] = fma_f2(bf2_to_f2(pn.z), vv, acc_n[2]);
        acc_n[3] = fma_f2(bf2_to_f2(pn.w), vv, acc_n[3]);
    }

    // unpack, clip to [0,1], output-layer partial dot
    float p = 0.f;
    {
        float4 wo_s0 = *(const float4*)(W_out + d);
        float4 wo_s1 = *(const float4*)(W_out + d + 4);
        float4 wo_n0 = *(const float4*)(W_out + FT_OUT + d);
        float4 wo_n1 = *(const float4*)(W_out + FT_OUT + d + 4);
        const float* ws = &wo_s0.x;   // 8 contiguous (two float4s on stack—use explicit)
        float hs[8], hn[8];
        unpack_f2(acc_s[0], hs[0], hs[1]);
        unpack_f2(acc_s[1], hs[2], hs[3]);
        unpack_f2(acc_s[2], hs[4], hs[5]);
        unpack_f2(acc_s[3], hs[6], hs[7]);
        unpack_f2(acc_n[0], hn[0], hn[1]);
        unpack_f2(acc_n[1], hn[2], hn[3]);
        unpack_f2(acc_n[2], hn[4], hn[5]);
        unpack_f2(acc_n[3], hn[6], hn[7]);
        float wsv[8] = {wo_s0.x, wo_s0.y, wo_s0.z, wo_s0.w,
                        wo_s1.x, wo_s1.y, wo_s1.z, wo_s1.w};
        float wnv[8] = {wo_n0.x, wo_n0.y, wo_n0.z, wo_n0.w,
                        wo_n1.x, wo_n1.y, wo_n1.z, wo_n1.w};
        (void)ws;
        #pragma unroll
        for (int k = 0; k < 8; k++) {
            float cs = fminf(fmaxf(hs[k], 0.f), 1.f);
            float cn = fminf(fmaxf(hn[k], 0.f), 1.f);
            p = fmaf(cs, wsv[k], p);
            p = fmaf(cn, wnv[k], p);
        }
    }

    // warp reduce (4 warps)
    #pragma unroll
    for (int off = 16; off > 0; off >>= 1)
        p += __shfl_down_sync(0xffffffffu, p, off);
    if ((tid & 31) == 0) s_red[tid >> 5] = p;
    __syncthreads();

    if (tid < (GTH_THREADS / 32)) {
        float q = s_red[tid];
        #pragma unroll
        for (int off = (GTH_THREADS / 64); off > 0; off >>= 1)
            q += __shfl_down_sync(0xfu, q, off);
        if (tid == 0) {
            float x = q + b_out[0];
            out[b] = 1.0f / (1.0f + expf(-x));
        }
    }
}

extern "C" void kernel_launch(void* const* d_in, const int* in_sizes, int n_in,
                              void* d_out, int out_size) {
    // metadata order:
    // 0 values, 1 stm_feat, 2 nstm_feat, 3 batch_idx, 4 W_ft, 5 b_ft,
    // 6 W_fft, 7 b_fft, 8 W_out, 9 b_out, 10 size
    const float* values    = (const float*)d_in[0];
    const int*   stm_feat  = (const int*)d_in[1];
    const int*   nstm_feat = (const int*)d_in[2];
    const float* W_ft      = (const float*)d_in[4];
    const float* b_ft      = (const float*)d_in[5];
    const float* W_fft     = (const float*)d_in[6];
    const float* b_fft     = (const float*)d_in[7];
    const float* W_out     = (const float*)d_in[8];
    const float* b_out     = (const float*)d_in[9];
    float* out = (float*)d_out;

    const int B = out_size;  // 8192

    build_comb_kernel<<<NFEAT, BLD_THREADS>>>(W_ft, W_fft);
    nnue_gather_kernel<<<B, GTH_THREADS>>>(values, stm_feat, nstm_feat,
                                           b_ft, b_fft, W_out, b_out, out);
}